// round 7
// baseline (speedup 1.0000x reference)
#include <cuda_runtime.h>
#include <cuda_bf16.h>
#include <math.h>

#define Nn 64
#define Tt 32
#define DA 1280
#define PP 16
#define HH 512
#define H4 2048
#define WD 300
#define VV 32000

// ---------------- device scratch (no allocs allowed) ----------------
__device__ float g_cwT[DA * HH];            // conv_w transposed [c][h]
__device__ float g_Aproj[Nn * PP * HH];     // [n*16+p][512]
__device__ float g_h[2][Nn * HH];           // double-buffered h
__device__ float g_c[Nn * HH];
__device__ float g_w[Nn * PP];              // attention weights for current step
__device__ float g_xa[Tt * Nn * H4];        // x@Wx + b, row r = t*64+n
__device__ float g_AW[Nn * PP * H4];        // Aproj@Wattn, [n*16+p][2048]
__device__ float g_hn[Nn * Tt * HH];        // h outputs, row r = n*32+t (vocab-GEMM A)

// ---------------- f32x2 packed helpers ----------------
__device__ __forceinline__ void fma2(unsigned long long& d, unsigned long long a,
                                     unsigned long long b) {
    asm("fma.rn.f32x2 %0, %1, %2, %0;" : "+l"(d) : "l"(a), "l"(b));
}
__device__ __forceinline__ unsigned long long pack2(float lo, float hi) {
    unsigned long long r;
    asm("mov.b64 %0, {%1, %2};" : "=l"(r) : "f"(lo), "f"(hi));
    return r;
}
__device__ __forceinline__ float2 unpack2(unsigned long long v) {
    float2 r;
    asm("mov.b64 {%0, %1}, %2;" : "=f"(r.x), "=f"(r.y) : "l"(v));
    return r;
}

// ---------------- K0: transpose conv_w [512][1280] -> g_cwT [1280][512] ----------------
__global__ void k_transpose(const float* __restrict__ w) {
    __shared__ float tile[32][33];
    int c0 = blockIdx.x * 32, h0 = blockIdx.y * 32;
    for (int i = threadIdx.y; i < 32; i += 8)
        tile[i][threadIdx.x] = w[(h0 + i) * DA + c0 + threadIdx.x];
    __syncthreads();
    for (int i = threadIdx.y; i < 32; i += 8)
        g_cwT[(c0 + i) * HH + h0 + threadIdx.x] = tile[threadIdx.x][i];
}

// ---------------- K1: Aproj[n][p][h] = sum_c A[n][c][p]*conv_w[h][c] + conv_b[h] ------
// grid 256 = 64 n * 4 colgroups(128 h), block 128
__global__ void k_conv(const float* __restrict__ A, const float* __restrict__ cb) {
    int n = blockIdx.x >> 2, cg = blockIdx.x & 3;
    int j = cg * 128 + threadIdx.x;
    __shared__ float a_sm[256 * 16];
    float acc[16];
#pragma unroll
    for (int p = 0; p < 16; p++) acc[p] = 0.f;
    for (int k0 = 0; k0 < DA; k0 += 256) {
        __syncthreads();
        const float* src = A + ((size_t)n * DA + k0) * 16;
        for (int idx = threadIdx.x; idx < 256 * 16; idx += 128) a_sm[idx] = src[idx];
        __syncthreads();
#pragma unroll 4
        for (int kk = 0; kk < 256; kk++) {
            float w = g_cwT[(k0 + kk) * HH + j];
            const float4* ar = (const float4*)&a_sm[kk * 16];
            float4 a0 = ar[0], a1 = ar[1], a2 = ar[2], a3 = ar[3];
            acc[0]  += a0.x * w; acc[1]  += a0.y * w; acc[2]  += a0.z * w; acc[3]  += a0.w * w;
            acc[4]  += a1.x * w; acc[5]  += a1.y * w; acc[6]  += a1.z * w; acc[7]  += a1.w * w;
            acc[8]  += a2.x * w; acc[9]  += a2.y * w; acc[10] += a2.z * w; acc[11] += a2.w * w;
            acc[12] += a3.x * w; acc[13] += a3.y * w; acc[14] += a3.z * w; acc[15] += a3.w * w;
        }
    }
    float bb = cb[j];
#pragma unroll
    for (int p = 0; p < 16; p++) g_Aproj[(n * 16 + p) * HH + j] = acc[p] + bb;
}

// ---------------- K1b: h0 = mean over p; c0 = h0 ----------------
__global__ void k_h0() {
    int n = blockIdx.x, h = threadIdx.x;
    float s = 0.f;
#pragma unroll
    for (int p = 0; p < 16; p++) s += g_Aproj[(n * 16 + p) * HH + h];
    s *= (1.f / 16.f);
    g_h[0][n * HH + h] = s;
    g_c[n * HH + h] = s;
}

// ---------------- K2: xa[r][j] = emb(cap)[r] @ Wx + b, r = t*64+n ----------------
// grid (16 colgroups of 128, 64 rowgroups of 32), block 128
__global__ void k_xa(const int* __restrict__ caps, const float* __restrict__ We,
                     const float* __restrict__ Wx, const float* __restrict__ bias) {
    int col = blockIdx.x * 128 + threadIdx.x;
    int r0 = blockIdx.y * 32;
    __shared__ int tok[32];
    __shared__ float x_sm[32 * 304];
    if (threadIdx.x < 32) {
        int rr = r0 + threadIdx.x;
        int n = rr & 63, t = rr >> 6;
        tok[threadIdx.x] = caps[n * Tt + t];
    }
    __syncthreads();
    for (int idx = threadIdx.x; idx < 32 * 300; idx += 128) {
        int r = idx / 300, c = idx - r * 300;
        x_sm[r * 304 + c] = We[(size_t)tok[r] * 300 + c];
    }
    __syncthreads();
    float acc[32];
#pragma unroll
    for (int r = 0; r < 32; r++) acc[r] = 0.f;
    for (int k0 = 0; k0 < 300; k0 += 4) {
        float w0 = Wx[(k0 + 0) * H4 + col];
        float w1 = Wx[(k0 + 1) * H4 + col];
        float w2 = Wx[(k0 + 2) * H4 + col];
        float w3 = Wx[(k0 + 3) * H4 + col];
#pragma unroll
        for (int r = 0; r < 32; r++) {
            float4 xv = *(const float4*)&x_sm[r * 304 + k0];
            acc[r] += xv.x * w0 + xv.y * w1 + xv.z * w2 + xv.w * w3;
        }
    }
    float bb = bias[col];
#pragma unroll
    for (int r = 0; r < 32; r++) g_xa[(size_t)(r0 + r) * H4 + col] = acc[r] + bb;
}

// ---------------- K3: AW[r][j] = Aproj[r][:] @ Wattn, r = n*16+p ----------------
// grid (16 colgroups of 128, 32 rowgroups of 32), block 128
__global__ void k_aw(const float* __restrict__ Wattn) {
    int col = blockIdx.x * 128 + threadIdx.x;
    int r0 = blockIdx.y * 32;
    __shared__ float a_sm[32 * 256];
    float acc[32];
#pragma unroll
    for (int r = 0; r < 32; r++) acc[r] = 0.f;
    for (int k0 = 0; k0 < HH; k0 += 256) {
        __syncthreads();
        for (int idx = threadIdx.x; idx < 32 * 256; idx += 128) {
            int r = idx >> 8, c = idx & 255;
            a_sm[idx] = g_Aproj[(r0 + r) * HH + k0 + c];
        }
        __syncthreads();
        for (int kk = 0; kk < 256; kk += 4) {
            float w0 = Wattn[(k0 + kk + 0) * H4 + col];
            float w1 = Wattn[(k0 + kk + 1) * H4 + col];
            float w2 = Wattn[(k0 + kk + 2) * H4 + col];
            float w3 = Wattn[(k0 + kk + 3) * H4 + col];
#pragma unroll
            for (int r = 0; r < 32; r++) {
                float4 av = *(const float4*)&a_sm[r * 256 + kk];
                acc[r] += av.x * w0 + av.y * w1 + av.z * w2 + av.w * w3;
            }
        }
    }
#pragma unroll
    for (int r = 0; r < 32; r++) g_AW[(size_t)(r0 + r) * H4 + col] = acc[r];
}

// ---------------- K4a: attention weights for step t ----------------
// grid 64 (one per n), block 256: 16 lanes per p
__global__ void k_attw(int t) {
    int rb = t & 1;
    int n = blockIdx.x;
    int tid = threadIdx.x;
    int p = tid >> 4, l = tid & 15;
    __shared__ float sc[16];
    const float* hv = g_h[rb] + n * HH;
    const float* av = g_Aproj + (n * 16 + p) * HH;
    float s = 0.f;
#pragma unroll 8
    for (int i = 0; i < 32; i++) {
        int k = l + i * 16;
        s += hv[k] * av[k];
    }
    s += __shfl_down_sync(0xffffffffu, s, 8, 16);
    s += __shfl_down_sync(0xffffffffu, s, 4, 16);
    s += __shfl_down_sync(0xffffffffu, s, 2, 16);
    s += __shfl_down_sync(0xffffffffu, s, 1, 16);
    if (l == 0) sc[p] = s * 0.04419417382415922f;  // 1/sqrt(512)
    __syncthreads();
    if (tid < 16) {
        float v = sc[tid];
        float m = v;
        for (int off = 8; off; off >>= 1) m = fmaxf(m, __shfl_xor_sync(0x0000ffffu, m, off, 16));
        float e = expf(v - m);
        float sum = e;
        for (int off = 8; off; off >>= 1) sum += __shfl_xor_sync(0x0000ffffu, sum, off, 16);
        g_w[n * 16 + tid] = e / sum;
    }
}

// ---------------- K4b: fused LSTM step ----------------
// a[n][j] = xa[t][n][j] + sum_k h[n][k]*Wh[k][j] + sum_p w[n][p]*AW[n][p][j]
// then gates, c/h update, h written into g_h[next] and g_hn.
// grid (32 hcolgroups of 16, 4 rowgroups of 16 n), block 256.
// Thread: c = tid&63 -> (gate = c>>4, hcl = c&15), ks = tid>>6 (k-slice of 128).
__global__ void k_step(const float* __restrict__ Wh, int t) {
    int rb = t & 1, wb = rb ^ 1;
    int hc0 = blockIdx.x * 16;
    int n0 = blockIdx.y * 16;
    __shared__ float h_sm[16][512];         // 32 KB
    __shared__ float red_sm[3][16][64];     // 12 KB (aliased as a_sm after use)
    __shared__ float w_sm[16][16];          // 1 KB
    int tid = threadIdx.x;
    // load h for this rowgroup (coalesced)
    for (int idx = tid; idx < 16 * 512; idx += 256) {
        int r = idx >> 9, k = idx & 511;
        h_sm[r][k] = g_h[rb][(n0 + r) * HH + k];
    }
    // load attention weights
    w_sm[tid >> 4][tid & 15] = g_w[(n0 + (tid >> 4)) * 16 + (tid & 15)];
    __syncthreads();

    int c = tid & 63;
    int ks = tid >> 6;
    int gate = c >> 4, hcl = c & 15;
    int j = gate * HH + hc0 + hcl;
    const float* whcol = Wh + j;

    float acc[16];
#pragma unroll
    for (int r = 0; r < 16; r++) acc[r] = 0.f;

    int kbeg = ks * 128;
    for (int k = kbeg; k < kbeg + 128; k += 4) {
        float w0 = whcol[(k + 0) * H4];
        float w1 = whcol[(k + 1) * H4];
        float w2 = whcol[(k + 2) * H4];
        float w3 = whcol[(k + 3) * H4];
#pragma unroll
        for (int r = 0; r < 16; r++) {
            float4 h4 = *(const float4*)&h_sm[r][k];
            acc[r] += h4.x * w0 + h4.y * w1 + h4.z * w2 + h4.w * w3;
        }
    }
    // attention combine: this k-slice handles 4 of the 16 spatial positions
#pragma unroll
    for (int pp = 0; pp < 4; pp++) {
        int p = ks * 4 + pp;
#pragma unroll
        for (int r = 0; r < 16; r++)
            acc[r] += w_sm[r][p] * g_AW[((size_t)(n0 + r) * 16 + p) * H4 + j];
    }
    if (ks) {
#pragma unroll
        for (int r = 0; r < 16; r++) red_sm[ks - 1][r][c] = acc[r];
    }
    __syncthreads();
    float aval[16];
    if (ks == 0) {
#pragma unroll
        for (int r = 0; r < 16; r++) {
            float a = acc[r] + red_sm[0][r][c] + red_sm[1][r][c] + red_sm[2][r][c];
            a += g_xa[((size_t)t * 64 + n0 + r) * H4 + j];
            aval[r] = a;
        }
    }
    __syncthreads();
    if (ks == 0) {
#pragma unroll
        for (int r = 0; r < 16; r++) red_sm[0][r][c] = aval[r];   // reuse as a_sm
    }
    __syncthreads();
    // gates: one (n, hcol) per thread
    {
        int r = tid >> 4, hl = tid & 15;
        float ai = red_sm[0][r][0 * 16 + hl];
        float af = red_sm[0][r][1 * 16 + hl];
        float ao = red_sm[0][r][2 * 16 + hl];
        float ag = red_sm[0][r][3 * 16 + hl];
        float gi = 1.f / (1.f + expf(-ai));
        float gf = 1.f / (1.f + expf(-af));
        float go = 1.f / (1.f + expf(-ao));
        float gg = tanhf(ag);
        int ng = n0 + r, hg = hc0 + hl;
        float cp = g_c[ng * HH + hg];
        float cn = gf * cp + gi * gg;
        float hn = go * tanhf(cn);
        g_c[ng * HH + hg] = cn;
        g_h[wb][ng * HH + hg] = hn;
        g_hn[((size_t)ng * Tt + t) * HH + hg] = hn;
    }
}

// ---------------- K5: vocab GEMM  out[r][v] = g_hn[r][:] @ Wv[:,v] + bv[v] ----------
// M=2048, N=32000, K=512. Tiles 128x128x16, 256 threads, 8x8 microtile, FFMA2.
// grid (16 M-blocks [fastest -> B-slab L2 reuse], 250 N-blocks).
__global__ __launch_bounds__(256, 2)
void k_vocab(const float* __restrict__ Wv, const float* __restrict__ bv,
             float* __restrict__ out) {
    __shared__ float As[16][128];
    __shared__ float Bs[16][128];
    int bm = blockIdx.x, bn = blockIdx.y;
    int tid = threadIdx.x;
    int tx = tid & 15, ty = tid >> 4;

    unsigned long long acc[8][4];
#pragma unroll
    for (int i = 0; i < 8; i++)
#pragma unroll
        for (int jj = 0; jj < 4; jj++) acc[i][jj] = 0ULL;

    int ar = tid >> 1;                // 0..127 : A row within tile
    int akq = (tid & 1) * 2;          // k-quad 0/2 (+1 each)
    int bk = tid >> 4;                // 0..15 : B k within tile
    int bcq = tid & 15;               // col-quads bcq, bcq+16
    const float* Ag = g_hn + (size_t)(bm * 128 + ar) * HH;
    const float* Bg = Wv + (size_t)bn * 128;

    for (int k0 = 0; k0 < 512; k0 += 16) {
        __syncthreads();
        float4 a0 = *(const float4*)&Ag[k0 + akq * 4];
        float4 a1 = *(const float4*)&Ag[k0 + akq * 4 + 4];
        As[akq * 4 + 0][ar] = a0.x;  As[akq * 4 + 1][ar] = a0.y;
        As[akq * 4 + 2][ar] = a0.z;  As[akq * 4 + 3][ar] = a0.w;
        As[akq * 4 + 4][ar] = a1.x;  As[akq * 4 + 5][ar] = a1.y;
        As[akq * 4 + 6][ar] = a1.z;  As[akq * 4 + 7][ar] = a1.w;
        float4 b0 = *(const float4*)&Bg[(size_t)(k0 + bk) * VV + bcq * 4];
        float4 b1 = *(const float4*)&Bg[(size_t)(k0 + bk) * VV + (bcq + 16) * 4];
        *(float4*)&Bs[bk][bcq * 4] = b0;
        *(float4*)&Bs[bk][(bcq + 16) * 4] = b1;
        __syncthreads();
#pragma unroll
        for (int k = 0; k < 16; k++) {
            float4 pa0 = *(const float4*)&As[k][ty * 8];
            float4 pa1 = *(const float4*)&As[k][ty * 8 + 4];
            unsigned long long rb[4];
            rb[0] = *(const unsigned long long*)&Bs[k][tx * 8 + 0];
            rb[1] = *(const unsigned long long*)&Bs[k][tx * 8 + 2];
            rb[2] = *(const unsigned long long*)&Bs[k][tx * 8 + 4];
            rb[3] = *(const unsigned long long*)&Bs[k][tx * 8 + 6];
            float ra[8] = {pa0.x, pa0.y, pa0.z, pa0.w, pa1.x, pa1.y, pa1.z, pa1.w};
#pragma unroll
            for (int i = 0; i < 8; i++) {
                unsigned long long a2 = pack2(ra[i], ra[i]);
#pragma unroll
                for (int jj = 0; jj < 4; jj++) fma2(acc[i][jj], a2, rb[jj]);
            }
        }
    }
    int row0 = bm * 128 + ty * 8;
    int col0 = bn * 128 + tx * 8;
    float bias[8];
#pragma unroll
    for (int jj = 0; jj < 8; jj++) bias[jj] = bv[col0 + jj];
#pragma unroll
    for (int i = 0; i < 8; i++) {
        float* orow = out + (size_t)(row0 + i) * VV + col0;
#pragma unroll
        for (int jj = 0; jj < 4; jj++) {
            float2 v = unpack2(acc[i][jj]);
            orow[jj * 2 + 0] = v.x + bias[jj * 2 + 0];
            orow[jj * 2 + 1] = v.y + bias[jj * 2 + 1];
        }
    }
}

// ---------------- launcher ----------------
extern "C" void kernel_launch(void* const* d_in, const int* in_sizes, int n_in,
                              void* d_out, int out_size) {
    const float* A      = (const float*)d_in[0];
    const int*   caps   = (const int*)  d_in[1];
    const float* conv_w = (const float*)d_in[2];
    const float* conv_b = (const float*)d_in[3];
    const float* Wx     = (const float*)d_in[4];
    const float* Wh     = (const float*)d_in[5];
    const float* Wattn  = (const float*)d_in[6];
    const float* b      = (const float*)d_in[7];
    const float* We     = (const float*)d_in[8];
    const float* Wv     = (const float*)d_in[9];
    const float* bv     = (const float*)d_in[10];
    float* out = (float*)d_out;

    k_transpose<<<dim3(DA / 32, HH / 32), dim3(32, 8)>>>(conv_w);
    k_conv<<<256, 128>>>(A, conv_b);
    k_h0<<<Nn, HH>>>();
    k_xa<<<dim3(16, 64), 128>>>(caps, We, Wx, b);
    k_aw<<<dim3(16, 32), 128>>>(Wattn);
    for (int t = 0; t < Tt; t++) {
        k_attw<<<Nn, 256>>>(t);
        k_step<<<dim3(32, 4), 256>>>(Wh, t);
    }
    k_vocab<<<dim3(16, 250), 256>>>(Wv, bv, out);
}

// round 9
// speedup vs baseline: 1.5204x; 1.5204x over previous
#include <cuda_runtime.h>
#include <cuda_bf16.h>
#include <math.h>
#include <stdint.h>

#define Nn 64
#define Tt 32
#define DA 1280
#define PP 16
#define HH 512
#define H4 2048
#define WD 300
#define VV 32000

// ---------------- device scratch (no allocs allowed) ----------------
__device__ float g_cwT[DA * HH];            // conv_w transposed [c][h]
__device__ float g_Aproj[Nn * PP * HH];     // [n*16+p][512]
__device__ float g_h[2][Nn * HH];           // double-buffered h
__device__ float g_c[Nn * HH];
__device__ float g_w[Nn * PP];              // attention weights for current step
__device__ float g_xa[Tt * Nn * H4];        // x@Wx + b, row r = t*64+n
__device__ float g_AW[Nn * PP * H4];        // Aproj@Wattn, [n*16+p][2048]
__device__ float g_hn[Nn * Tt * HH];        // h outputs, row r = n*32+t (vocab-GEMM A)

// bf16-split operands for the HMMA vocab GEMM (K-major)
__device__ __align__(16) __nv_bfloat16 g_Ah[Nn * Tt * HH];   // [2048][512]
__device__ __align__(16) __nv_bfloat16 g_Al[Nn * Tt * HH];
__device__ __align__(16) __nv_bfloat16 g_BhT[(size_t)VV * HH];   // [32000][512]
__device__ __align__(16) __nv_bfloat16 g_BlT[(size_t)VV * HH];

// ---------------- portable PTX helpers (sm_80+ features only) ----------------
__device__ __forceinline__ uint32_t smem_u32(const void* p) {
    uint32_t a;
    asm("{ .reg .u64 t; cvta.to.shared.u64 t, %1; cvt.u32.u64 %0, t; }" : "=r"(a) : "l"(p));
    return a;
}
__device__ __forceinline__ void cpasync16(uint32_t dst, const void* src) {
    asm volatile("cp.async.cg.shared.global [%0], [%1], 16;" :: "r"(dst), "l"(src) : "memory");
}
__device__ __forceinline__ void cp_commit() {
    asm volatile("cp.async.commit_group;" ::: "memory");
}
__device__ __forceinline__ void ldmx4(uint32_t* r, uint32_t addr) {
    asm volatile("ldmatrix.sync.aligned.m8n8.x4.shared.b16 {%0,%1,%2,%3}, [%4];"
                 : "=r"(r[0]), "=r"(r[1]), "=r"(r[2]), "=r"(r[3]) : "r"(addr));
}
__device__ __forceinline__ void mma16816(float* d, const uint32_t* a, uint32_t b0, uint32_t b1) {
    asm volatile(
        "mma.sync.aligned.m16n8k16.row.col.f32.bf16.bf16.f32 "
        "{%0,%1,%2,%3}, {%4,%5,%6,%7}, {%8,%9}, {%0,%1,%2,%3};"
        : "+f"(d[0]), "+f"(d[1]), "+f"(d[2]), "+f"(d[3])
        : "r"(a[0]), "r"(a[1]), "r"(a[2]), "r"(a[3]), "r"(b0), "r"(b1));
}

// ---------------- K0: transpose conv_w [512][1280] -> g_cwT [1280][512] ----------------
__global__ void k_transpose(const float* __restrict__ w) {
    __shared__ float tile[32][33];
    int c0 = blockIdx.x * 32, h0 = blockIdx.y * 32;
    for (int i = threadIdx.y; i < 32; i += 8)
        tile[i][threadIdx.x] = w[(h0 + i) * DA + c0 + threadIdx.x];
    __syncthreads();
    for (int i = threadIdx.y; i < 32; i += 8)
        g_cwT[(c0 + i) * HH + h0 + threadIdx.x] = tile[threadIdx.x][i];
}

// ---------------- K1: Aproj[n][p][h] = sum_c A[n][c][p]*conv_w[h][c] + conv_b[h] ------
__global__ void k_conv(const float* __restrict__ A, const float* __restrict__ cb) {
    int n = blockIdx.x >> 2, cg = blockIdx.x & 3;
    int j = cg * 128 + threadIdx.x;
    __shared__ float a_sm[256 * 16];
    float acc[16];
#pragma unroll
    for (int p = 0; p < 16; p++) acc[p] = 0.f;
    for (int k0 = 0; k0 < DA; k0 += 256) {
        __syncthreads();
        const float* src = A + ((size_t)n * DA + k0) * 16;
        for (int idx = threadIdx.x; idx < 256 * 16; idx += 128) a_sm[idx] = src[idx];
        __syncthreads();
#pragma unroll 4
        for (int kk = 0; kk < 256; kk++) {
            float w = g_cwT[(k0 + kk) * HH + j];
            const float4* ar = (const float4*)&a_sm[kk * 16];
            float4 a0 = ar[0], a1 = ar[1], a2 = ar[2], a3 = ar[3];
            acc[0]  += a0.x * w; acc[1]  += a0.y * w; acc[2]  += a0.z * w; acc[3]  += a0.w * w;
            acc[4]  += a1.x * w; acc[5]  += a1.y * w; acc[6]  += a1.z * w; acc[7]  += a1.w * w;
            acc[8]  += a2.x * w; acc[9]  += a2.y * w; acc[10] += a2.z * w; acc[11] += a2.w * w;
            acc[12] += a3.x * w; acc[13] += a3.y * w; acc[14] += a3.z * w; acc[15] += a3.w * w;
        }
    }
    float bb = cb[j];
#pragma unroll
    for (int p = 0; p < 16; p++) g_Aproj[(n * 16 + p) * HH + j] = acc[p] + bb;
}

// ---------------- K1b: h0 = mean over p; c0 = h0 ----------------
__global__ void k_h0() {
    int n = blockIdx.x, h = threadIdx.x;
    float s = 0.f;
#pragma unroll
    for (int p = 0; p < 16; p++) s += g_Aproj[(n * 16 + p) * HH + h];
    s *= (1.f / 16.f);
    g_h[0][n * HH + h] = s;
    g_c[n * HH + h] = s;
}

// ---------------- K2: xa[r][j] = emb(cap)[r] @ Wx + b, r = t*64+n ----------------
__global__ void k_xa(const int* __restrict__ caps, const float* __restrict__ We,
                     const float* __restrict__ Wx, const float* __restrict__ bias) {
    int col = blockIdx.x * 128 + threadIdx.x;
    int r0 = blockIdx.y * 32;
    __shared__ int tok[32];
    __shared__ float x_sm[32 * 304];
    if (threadIdx.x < 32) {
        int rr = r0 + threadIdx.x;
        int n = rr & 63, t = rr >> 6;
        tok[threadIdx.x] = caps[n * Tt + t];
    }
    __syncthreads();
    for (int idx = threadIdx.x; idx < 32 * 300; idx += 128) {
        int r = idx / 300, c = idx - r * 300;
        x_sm[r * 304 + c] = We[(size_t)tok[r] * 300 + c];
    }
    __syncthreads();
    float acc[32];
#pragma unroll
    for (int r = 0; r < 32; r++) acc[r] = 0.f;
    float w0 = Wx[col], w1 = Wx[H4 + col], w2 = Wx[2 * H4 + col], w3 = Wx[3 * H4 + col];
    for (int k0 = 0; k0 < 300; k0 += 4) {
        float n0 = 0.f, n1 = 0.f, n2 = 0.f, n3 = 0.f;
        if (k0 + 4 < 300) {
            const float* wp = Wx + (size_t)(k0 + 4) * H4 + col;
            n0 = wp[0]; n1 = wp[H4]; n2 = wp[2 * H4]; n3 = wp[3 * H4];
        }
#pragma unroll
        for (int r = 0; r < 32; r++) {
            float4 xv = *(const float4*)&x_sm[r * 304 + k0];
            acc[r] += xv.x * w0 + xv.y * w1 + xv.z * w2 + xv.w * w3;
        }
        w0 = n0; w1 = n1; w2 = n2; w3 = n3;
    }
    float bb = bias[col];
#pragma unroll
    for (int r = 0; r < 32; r++) g_xa[(size_t)(r0 + r) * H4 + col] = acc[r] + bb;
}

// ---------------- K3: AW[r][j] = Aproj[r][:] @ Wattn, r = n*16+p ----------------
__global__ void k_aw(const float* __restrict__ Wattn) {
    int col = blockIdx.x * 128 + threadIdx.x;
    int r0 = blockIdx.y * 32;
    __shared__ float a_sm[32 * 256];
    float acc[32];
#pragma unroll
    for (int r = 0; r < 32; r++) acc[r] = 0.f;
    for (int k0 = 0; k0 < HH; k0 += 256) {
        __syncthreads();
        for (int idx = threadIdx.x; idx < 32 * 256; idx += 128) {
            int r = idx >> 8, c = idx & 255;
            a_sm[idx] = g_Aproj[(r0 + r) * HH + k0 + c];
        }
        __syncthreads();
        for (int kk = 0; kk < 256; kk += 4) {
            float w0 = Wattn[(k0 + kk + 0) * H4 + col];
            float w1 = Wattn[(k0 + kk + 1) * H4 + col];
            float w2 = Wattn[(k0 + kk + 2) * H4 + col];
            float w3 = Wattn[(k0 + kk + 3) * H4 + col];
#pragma unroll
            for (int r = 0; r < 32; r++) {
                float4 av = *(const float4*)&a_sm[r * 256 + kk];
                acc[r] += av.x * w0 + av.y * w1 + av.z * w2 + av.w * w3;
            }
        }
    }
#pragma unroll
    for (int r = 0; r < 32; r++) g_AW[(size_t)(r0 + r) * H4 + col] = acc[r];
}

// ---------------- K4a: attention weights for step t ----------------
__global__ void k_attw(int t) {
    int rb = t & 1;
    int n = blockIdx.x;
    int tid = threadIdx.x;
    int p = tid >> 4, l = tid & 15;
    __shared__ float sc[16];
    const float* hv = g_h[rb] + n * HH;
    const float* av = g_Aproj + (n * 16 + p) * HH;
    float s = 0.f;
#pragma unroll 8
    for (int i = 0; i < 32; i++) {
        int k = l + i * 16;
        s += hv[k] * av[k];
    }
    s += __shfl_down_sync(0xffffffffu, s, 8, 16);
    s += __shfl_down_sync(0xffffffffu, s, 4, 16);
    s += __shfl_down_sync(0xffffffffu, s, 2, 16);
    s += __shfl_down_sync(0xffffffffu, s, 1, 16);
    if (l == 0) sc[p] = s * 0.04419417382415922f;  // 1/sqrt(512)
    __syncthreads();
    if (tid < 16) {
        float v = sc[tid];
        float m = v;
        for (int off = 8; off; off >>= 1) m = fmaxf(m, __shfl_xor_sync(0x0000ffffu, m, off, 16));
        float e = expf(v - m);
        float sum = e;
        for (int off = 8; off; off >>= 1) sum += __shfl_xor_sync(0x0000ffffu, sum, off, 16);
        g_w[n * 16 + tid] = e / sum;
    }
}

// ---------------- K4b: fused LSTM step ----------------
__global__ void k_step(const float* __restrict__ Wh, int t) {
    int rb = t & 1, wb = rb ^ 1;
    int hc0 = blockIdx.x * 16;
    int n0 = blockIdx.y * 16;
    __shared__ float h_sm[16][512];
    __shared__ float red_sm[3][16][64];
    __shared__ float w_sm[16][16];
    int tid = threadIdx.x;
    for (int idx = tid; idx < 16 * 512; idx += 256) {
        int r = idx >> 9, k = idx & 511;
        h_sm[r][k] = g_h[rb][(n0 + r) * HH + k];
    }
    w_sm[tid >> 4][tid & 15] = g_w[(n0 + (tid >> 4)) * 16 + (tid & 15)];
    __syncthreads();

    int c = tid & 63;
    int ks = tid >> 6;
    int gate = c >> 4, hcl = c & 15;
    int j = gate * HH + hc0 + hcl;
    const float* whcol = Wh + j;

    float acc[16];
#pragma unroll
    for (int r = 0; r < 16; r++) acc[r] = 0.f;

    int kbeg = ks * 128;
    for (int k = kbeg; k < kbeg + 128; k += 4) {
        float w0 = whcol[(k + 0) * H4];
        float w1 = whcol[(k + 1) * H4];
        float w2 = whcol[(k + 2) * H4];
        float w3 = whcol[(k + 3) * H4];
#pragma unroll
        for (int r = 0; r < 16; r++) {
            float4 h4 = *(const float4*)&h_sm[r][k];
            acc[r] += h4.x * w0 + h4.y * w1 + h4.z * w2 + h4.w * w3;
        }
    }
#pragma unroll
    for (int pp = 0; pp < 4; pp++) {
        int p = ks * 4 + pp;
#pragma unroll
        for (int r = 0; r < 16; r++)
            acc[r] += w_sm[r][p] * g_AW[((size_t)(n0 + r) * 16 + p) * H4 + j];
    }
    if (ks) {
#pragma unroll
        for (int r = 0; r < 16; r++) red_sm[ks - 1][r][c] = acc[r];
    }
    __syncthreads();
    float aval[16];
    if (ks == 0) {
#pragma unroll
        for (int r = 0; r < 16; r++) {
            float a = acc[r] + red_sm[0][r][c] + red_sm[1][r][c] + red_sm[2][r][c];
            a += g_xa[((size_t)t * 64 + n0 + r) * H4 + j];
            aval[r] = a;
        }
    }
    __syncthreads();
    if (ks == 0) {
#pragma unroll
        for (int r = 0; r < 16; r++) red_sm[0][r][c] = aval[r];
    }
    __syncthreads();
    {
        int r = tid >> 4, hl = tid & 15;
        float ai = red_sm[0][r][0 * 16 + hl];
        float af = red_sm[0][r][1 * 16 + hl];
        float ao = red_sm[0][r][2 * 16 + hl];
        float ag = red_sm[0][r][3 * 16 + hl];
        float gi = 1.f / (1.f + expf(-ai));
        float gf = 1.f / (1.f + expf(-af));
        float go = 1.f / (1.f + expf(-ao));
        float gg = tanhf(ag);
        int ng = n0 + r, hg = hc0 + hl;
        float cp = g_c[ng * HH + hg];
        float cn = gf * cp + gi * gg;
        float hn = go * tanhf(cn);
        g_c[ng * HH + hg] = cn;
        g_h[wb][ng * HH + hg] = hn;
        g_hn[((size_t)ng * Tt + t) * HH + hg] = hn;
    }
}

// ---------------- K_convB: Wv [512][32000] fp32 -> BhT/BlT [32000][512] bf16-split ----
__global__ void k_convB(const float* __restrict__ Wv) {
    __shared__ float tile[32][33];
    int v0 = blockIdx.x * 32, k0 = blockIdx.y * 32;
    for (int i = threadIdx.y; i < 32; i += 8)
        tile[i][threadIdx.x] = Wv[(size_t)(k0 + i) * VV + v0 + threadIdx.x];
    __syncthreads();
    for (int i = threadIdx.y; i < 32; i += 8) {
        float x = tile[threadIdx.x][i];     // = Wv[k0+tx][v0+i]
        __nv_bfloat16 hi = __float2bfloat16(x);
        float lo = x - __bfloat162float(hi);
        size_t o = (size_t)(v0 + i) * HH + k0 + threadIdx.x;
        g_BhT[o] = hi;
        g_BlT[o] = __float2bfloat16(lo);
    }
}

// ---------------- K_convA: g_hn fp32 -> Ah/Al bf16-split ----------------
__global__ void k_convA() {
    int i = blockIdx.x * 256 + threadIdx.x;
    float x = g_hn[i];
    __nv_bfloat16 hi = __float2bfloat16(x);
    g_Ah[i] = hi;
    g_Al[i] = __float2bfloat16(x - __bfloat162float(hi));
}

// ---------------- K5: HMMA bf16-split vocab GEMM ----------------
// D[2048,32000] = hn @ Wv + bv  via  Ah@Bh + Al@Bh + Ah@Bl  (fp32 accum).
// CTA tile 128x128x32, 256 threads (4 M-warps x 2 N-warps, 32x64 per warp),
// cp.async double buffer, 80B SMEM row pitch (conflict-free ldmatrix).
#define VBUF 40960   // bytes per pipeline buffer: AH|AL|BH|BL each 128*80
__global__ __launch_bounds__(256, 1)
void k_vocab_mma(const float* __restrict__ bv, float* __restrict__ out) {
    extern __shared__ char smv[];
    uint32_t sb = smem_u32(smv);
    int tid = threadIdx.x;
    int wid = tid >> 5, lane = tid & 31;
    int warp_m = wid & 3;   // 4 warps * 32 rows
    int warp_n = wid >> 2;  // 2 warps * 64 cols
    int bm = blockIdx.x, bn = blockIdx.y;

    const __nv_bfloat16* Ah0 = g_Ah + (size_t)bm * 128 * HH;
    const __nv_bfloat16* Al0 = g_Al + (size_t)bm * 128 * HH;
    const __nv_bfloat16* Bh0 = g_BhT + (size_t)bn * 128 * HH;
    const __nv_bfloat16* Bl0 = g_BlT + (size_t)bn * 128 * HH;

    float acc[2][8][4];
#pragma unroll
    for (int a = 0; a < 2; a++)
#pragma unroll
        for (int t = 0; t < 8; t++)
#pragma unroll
            for (int k = 0; k < 4; k++) acc[a][t][k] = 0.f;

    // issue cp.async loads for K-chunk `chunk` into buffer b
    auto issue = [&](int chunk, int b) {
        int k0 = chunk * 32;
        uint32_t base = sb + b * VBUF;
#pragma unroll
        for (int j = 0; j < 2; j++) {
            int idx = tid + j * 256;
            int r = idx >> 2, s = idx & 3;
            uint32_t doff = r * 80 + s * 16;
            size_t goff = (size_t)r * HH + k0 + s * 8;
            cpasync16(base + doff,          Ah0 + goff);
            cpasync16(base + 10240 + doff,  Al0 + goff);
            cpasync16(base + 20480 + doff,  Bh0 + goff);
            cpasync16(base + 30720 + doff,  Bl0 + goff);
        }
        cp_commit();
    };

    issue(0, 0);
    for (int i = 0; i < 16; i++) {
        int b = i & 1;
        if (i < 15) issue(i + 1, b ^ 1);
        if (i < 15) asm volatile("cp.async.wait_group 1;" ::: "memory");
        else        asm volatile("cp.async.wait_group 0;" ::: "memory");
        __syncthreads();

        uint32_t abase = sb + b * VBUF;
#pragma unroll
        for (int kc = 0; kc < 2; kc++) {
            uint32_t ah[2][4], al[2][4], bh[4][4], bl[4][4];
#pragma unroll
            for (int tm = 0; tm < 2; tm++) {
                int row = warp_m * 32 + tm * 16 + (lane & 15);
                uint32_t ad = abase + row * 80 + kc * 32 + (lane >> 4) * 16;
                ldmx4(ah[tm], ad);
                ldmx4(al[tm], ad + 10240);
            }
#pragma unroll
            for (int g = 0; g < 4; g++) {
                int col = warp_n * 64 + g * 16 + (lane & 15);
                uint32_t bd = abase + 20480 + col * 80 + kc * 32 + (lane >> 4) * 16;
                ldmx4(bh[g], bd);
                ldmx4(bl[g], bd + 10240);
            }
#pragma unroll
            for (int tm = 0; tm < 2; tm++)
#pragma unroll
                for (int tn = 0; tn < 8; tn++) {
                    int g = tn >> 1, p = tn & 1;
                    mma16816(acc[tm][tn], ah[tm], bh[g][p], bh[g][p + 2]);
                    mma16816(acc[tm][tn], al[tm], bh[g][p], bh[g][p + 2]);
                    mma16816(acc[tm][tn], ah[tm], bl[g][p], bl[g][p + 2]);
                }
        }
        __syncthreads();
    }

    // epilogue: add bias, write float2 per fragment half
#pragma unroll
    for (int tm = 0; tm < 2; tm++) {
        int row = bm * 128 + warp_m * 32 + tm * 16 + (lane >> 2);
#pragma unroll
        for (int tn = 0; tn < 8; tn++) {
            int col = bn * 128 + warp_n * 64 + tn * 8 + (lane & 3) * 2;
            float b0 = bv[col], b1 = bv[col + 1];
            float2 v0 = make_float2(acc[tm][tn][0] + b0, acc[tm][tn][1] + b1);
            float2 v1 = make_float2(acc[tm][tn][2] + b0, acc[tm][tn][3] + b1);
            *(float2*)&out[(size_t)row * VV + col] = v0;
            *(float2*)&out[(size_t)(row + 8) * VV + col] = v1;
        }
    }
}

// ---------------- launcher ----------------
extern "C" void kernel_launch(void* const* d_in, const int* in_sizes, int n_in,
                              void* d_out, int out_size) {
    const float* A      = (const float*)d_in[0];
    const int*   caps   = (const int*)  d_in[1];
    const float* conv_w = (const float*)d_in[2];
    const float* conv_b = (const float*)d_in[3];
    const float* Wx     = (const float*)d_in[4];
    const float* Wh     = (const float*)d_in[5];
    const float* Wattn  = (const float*)d_in[6];
    const float* b      = (const float*)d_in[7];
    const float* We     = (const float*)d_in[8];
    const float* Wv     = (const float*)d_in[9];
    const float* bv     = (const float*)d_in[10];
    float* out = (float*)d_out;

    cudaFuncSetAttribute(k_vocab_mma, cudaFuncAttributeMaxDynamicSharedMemorySize, 2 * VBUF);

    k_convB<<<dim3(VV / 32, HH / 32), dim3(32, 8)>>>(Wv);   // off the LSTM critical path
    k_transpose<<<dim3(DA / 32, HH / 32), dim3(32, 8)>>>(conv_w);
    k_conv<<<256, 128>>>(A, conv_b);
    k_h0<<<Nn, HH>>>();
    k_xa<<<dim3(16, 64), 128>>>(caps, We, Wx, b);
    k_aw<<<dim3(16, 32), 128>>>(Wattn);
    for (int t = 0; t < Tt; t++) {
        k_attw<<<Nn, 256>>>(t);
        k_step<<<dim3(32, 4), 256>>>(Wh, t);
    }
    k_convA<<<(Nn * Tt * HH) / 256, 256>>>();
    k_vocab_mma<<<dim3(16, 250), 256, 2 * VBUF>>>(bv, out);
}